// round 10
// baseline (speedup 1.0000x reference)
#include <cuda_runtime.h>
#include <cuda_fp16.h>
#include <cstdint>

#define NA 100000
#define NE 200000
#define NF 100000
#define DD 128
#define NEDGE 400000
#define TOTDST 700000
#define TOTEDGE 2000000
#define TOTSRC 400000   // xa + xe + xf rows

// ---------------- scratch (device globals: allocation-free) ----------------
__device__ uint32_t g_xh32[(size_t)TOTSRC * 64];   // 102.4 MB  [xa|xe|xf] rows x 128 halves
__device__ uint32_t g_wh32[5 * 2 * 8192];          // 5 types x {wl,wr} x 128x128 halves
__device__ int   g_cnt[TOTDST];
__device__ int   g_rowstart[TOTDST];
__device__ int   g_cursor[TOTDST];
__device__ int   g_edge_src[TOTEDGE];
__device__ int   g_bsums[256];

// ---------------- merged pre-pass: x->fp16 (y=0..2), zero cnt (y=3), w->fp16 (y=4) ----------------
__global__ void k_pre(const float* __restrict__ xa, const float* __restrict__ xe,
                      const float* __restrict__ xf,
                      const float* p0, const float* p1, const float* p2, const float* p3,
                      const float* p4, const float* p5, const float* p6, const float* p7,
                      const float* p8, const float* p9) {
    int y = blockIdx.y;
    int i = blockIdx.x * 256 + threadIdx.x;
    if (y < 3) {
        const float* src = (y == 0) ? xa : (y == 1) ? xe : xf;
        int rows = (y == 1) ? NE : NA;
        size_t dstoff = (y == 0) ? 0 : (y == 1) ? (size_t)NA * 32 : (size_t)(NA + NE) * 32;
        if (i >= rows * 32) return;
        float4 v = ((const float4*)src)[i];
        __half2 a = __floats2half2_rn(v.x, v.y);
        __half2 b = __floats2half2_rn(v.z, v.w);
        uint32_t* d = g_xh32 + dstoff * 2 + (size_t)i * 2;
        d[0] = *(uint32_t*)&a;
        d[1] = *(uint32_t*)&b;
    } else if (y == 3) {
        if (i < TOTDST) g_cnt[i] = 0;
    } else {
        if (i >= 10 * 4096) return;
        int j = i >> 12;
        int w = i & 4095;
        const float* src = (j == 0) ? p0 : (j == 1) ? p1 : (j == 2) ? p2 : (j == 3) ? p3 :
                           (j == 4) ? p4 : (j == 5) ? p5 : (j == 6) ? p6 : (j == 7) ? p7 :
                           (j == 8) ? p8 : p9;
        float4 v = ((const float4*)src)[w];
        __half2 a = __floats2half2_rn(v.x, v.y);
        __half2 b = __floats2half2_rn(v.z, v.w);
        uint32_t* d = g_wh32 + (size_t)j * 8192 + (size_t)w * 2;
        d[0] = *(uint32_t*)&a;
        d[1] = *(uint32_t*)&b;
    }
}

// ---------------- batched CSR build ----------------
__device__ __forceinline__ int dst_off_of(int t) {
    return (t == 0) ? 0 : (t == 1) ? 200000 : (t == 2) ? 300000 : (t == 3) ? 400000 : 500000;
}

__global__ void k_hist(const int* d0, const int* d1, const int* d2, const int* d3, const int* d4) {
    int e = blockIdx.x * 256 + threadIdx.x;
    if (e >= NEDGE) return;
    int t = blockIdx.y;
    const int* di = (t == 0) ? d0 : (t == 1) ? d1 : (t == 2) ? d2 : (t == 3) ? d3 : d4;
    atomicAdd(&g_cnt[dst_off_of(t) + di[e]], 1);
}

__global__ void k_scan1() {
    __shared__ int s[1024];
    int t = threadIdx.x;
    int base = blockIdx.x * 4096;
    int v[4];
    int sum = 0;
#pragma unroll
    for (int j = 0; j < 4; j++) {
        int idx = base + t * 4 + j;
        v[j] = (idx < TOTDST) ? g_cnt[idx] : 0;
        sum += v[j];
    }
    s[t] = sum;
    __syncthreads();
    for (int off = 1; off < 1024; off <<= 1) {
        int x = (t >= off) ? s[t - off] : 0;
        __syncthreads();
        if (t >= off) s[t] += x;
        __syncthreads();
    }
    int excl = s[t] - sum;
    if (t == 1023) g_bsums[blockIdx.x] = s[1023];
    int run = excl;
#pragma unroll
    for (int j = 0; j < 4; j++) {
        int idx = base + t * 4 + j;
        if (idx < TOTDST) g_rowstart[idx] = run;
        run += v[j];
    }
}

__global__ void k_scan2(int nb) {
    __shared__ int s[256];
    int t = threadIdx.x;
    int v = (t < nb) ? g_bsums[t] : 0;
    s[t] = v;
    __syncthreads();
    for (int off = 1; off < 256; off <<= 1) {
        int x = (t >= off) ? s[t - off] : 0;
        __syncthreads();
        s[t] += x;
        __syncthreads();
    }
    if (t < nb) g_bsums[t] = s[t] - v;
}

__global__ void k_scan3() {
    int i = blockIdx.x * blockDim.x + threadIdx.x;
    if (i < TOTDST) {
        int r = g_rowstart[i] + g_bsums[i >> 12];
        g_rowstart[i] = r;
        g_cursor[i] = r;
    }
}

__global__ void k_scatter(const int* s0, const int* s1, const int* s2, const int* s3, const int* s4,
                          const int* d0, const int* d1, const int* d2, const int* d3, const int* d4) {
    int e = blockIdx.x * 256 + threadIdx.x;
    if (e >= NEDGE) return;
    int t = blockIdx.y;
    const int* si = (t == 0) ? s0 : (t == 1) ? s1 : (t == 2) ? s2 : (t == 3) ? s3 : s4;
    const int* di = (t == 0) ? d0 : (t == 1) ? d1 : (t == 2) ? d2 : (t == 3) ? d3 : d4;
    int d = dst_off_of(t) + di[e];
    int p = atomicAdd(&g_cursor[d], 1);
    g_edge_src[p] = si[e];
}

// ---------------- fused aggregate + dual-type GEMM + normalize + combine ----------------
// Phase A: 8 rows in flight per warp (4 lanes x 64B per row), edge unroll-2 ->
// 8 outstanding LDG.128 per lane, 4 row-iterations per warp.
// Phase B: two K=256 GEMMs back-to-back.

#define SROW 12      // staged-tile row stride (words)
#define AROW 68      // agg tile row stride (words); 68 mod 32 == 4 -> conflict-free frags
#define AGGW 8704    // words per agg tile (128 x AROW)
#define AB 782       // ceil(NA/128)
#define EB 1563      // ceil(NE/128)
#define SMEM_WORDS (6144 + 2 * AGGW + 128)

__global__ __launch_bounds__(256, 2)
void k_fused(const float* __restrict__ b0, const float* __restrict__ b1,
             const float* __restrict__ b2, const float* __restrict__ b3,
             const float* __restrict__ b4, float* __restrict__ out)
{
    extern __shared__ uint32_t dyn[];
    uint32_t* sW   = dyn;                    // 2 x 1536
    uint32_t* sX   = dyn + 3072;             // 2 x 1536
    uint32_t* sAgg = dyn + 6144;             // 2 x 8704
    float*    sSS  = (float*)(dyn + 6144 + 2 * AGGW);  // 128

    const int tid = threadIdx.x;
    const int lane = tid & 31;
    const int warpId = tid >> 5;
    const int warpN = warpId & 1;
    const int warpM = warpId >> 1;
    const int g = lane >> 2;
    const int tg = lane & 3;

    int b = blockIdx.x;
    int kind, mblk;
    if (b < AB) { kind = 0; mblk = b; }
    else if (b < AB + EB) { kind = 1; mblk = b - AB; }
    else { kind = 2; mblk = b - (AB + EB); }
    const int m0 = mblk * 128;
    const int ndst = (kind == 1) ? NE : NA;
    const size_t xRowOff = (kind == 0) ? 0 : (kind == 1) ? (size_t)NA : (size_t)(NA + NE);
    float* osec = out + ((kind == 0) ? 0 : (kind == 1) ? (size_t)NA * DD : (size_t)(NA + NE) * DD);
    const int tA = (kind == 0) ? 2 : (kind == 1) ? 0 : 1;
    const int tB = (kind == 0) ? -1 : (kind == 1) ? 4 : 3;
    const int ntypes = (kind == 0) ? 1 : 2;

    const int lr = tid & 127;
    const bool isW = tid >= 128;

    // ---- phase A: aggregate (both types); 8 rows/warp, 4 lanes x 64B per row ----
    {
        int rowsel = lane >> 2;   // 0..7: which of the warp's 8 concurrent rows
        int l4 = lane & 3;        // 0..3: 64B slice within the 256B row
        int total = 128 * ntypes;
        for (int rr = warpId * 8 + rowsel; rr < total; rr += 64) {
            int it = rr >> 7;
            int r = rr & 127;
            int t = (it == 0) ? tA : tB;
            int dOff = dst_off_of(t);
            size_t sOff = (t <= 1) ? 0 : (t <= 3) ? (size_t)NA : (size_t)(NA + NE);
            int m = m0 + r;
            float f[32];
#pragma unroll
            for (int q = 0; q < 32; q++) f[q] = 0.f;
            int cnt = 0;
            if (m < ndst) {
                int gid = dOff + m;
                int start = __ldg(&g_rowstart[gid]);
                cnt = __ldg(&g_cnt[gid]);
                for (int jb = 0; jb < cnt; jb += 2) {
                    int ss[2];
                    uint4 v[2][4];
#pragma unroll
                    for (int k = 0; k < 2; k++)
                        ss[k] = (jb + k < cnt) ? __ldg(&g_edge_src[start + jb + k]) : -1;
#pragma unroll
                    for (int k = 0; k < 2; k++) {
                        if (ss[k] >= 0) {
                            const uint4* p = (const uint4*)(g_xh32 + ((size_t)sOff + ss[k]) * 64 + l4 * 16);
                            v[k][0] = __ldg(p);
                            v[k][1] = __ldg(p + 1);
                            v[k][2] = __ldg(p + 2);
                            v[k][3] = __ldg(p + 3);
                        } else {
                            v[k][0] = make_uint4(0, 0, 0, 0);
                            v[k][1] = v[k][0];
                            v[k][2] = v[k][0];
                            v[k][3] = v[k][0];
                        }
                    }
#pragma unroll
                    for (int k = 0; k < 2; k++)
#pragma unroll
                        for (int u = 0; u < 4; u++) {
                            __half2 h; float2 q2;
                            h = *(__half2*)&v[k][u].x; q2 = __half22float2(h); f[u*8+0] += q2.x; f[u*8+1] += q2.y;
                            h = *(__half2*)&v[k][u].y; q2 = __half22float2(h); f[u*8+2] += q2.x; f[u*8+3] += q2.y;
                            h = *(__half2*)&v[k][u].z; q2 = __half22float2(h); f[u*8+4] += q2.x; f[u*8+5] += q2.y;
                            h = *(__half2*)&v[k][u].w; q2 = __half22float2(h); f[u*8+6] += q2.x; f[u*8+7] += q2.y;
                        }
                }
            }
            float inv = 1.0f / (float)(cnt > 1 ? cnt : 1);
            uint4* dst = (uint4*)(sAgg + it * AGGW + r * AROW + l4 * 16);
#pragma unroll
            for (int u = 0; u < 4; u++) {
                uint4 o;
                __half2 h0 = __floats2half2_rn(f[u*8+0] * inv, f[u*8+1] * inv); o.x = *(uint32_t*)&h0;
                __half2 h1 = __floats2half2_rn(f[u*8+2] * inv, f[u*8+3] * inv); o.y = *(uint32_t*)&h1;
                __half2 h2 = __floats2half2_rn(f[u*8+4] * inv, f[u*8+5] * inv); o.z = *(uint32_t*)&h2;
                __half2 h3 = __floats2half2_rn(f[u*8+6] * inv, f[u*8+7] * inv); o.w = *(uint32_t*)&h3;
                dst[u] = o;
            }
        }
    }
    __syncthreads();

    // ---- phase B: per type, K=256 GEMM + epilogue ----
    for (int it = 0; it < ntypes; it++) {
        const int t = (it == 0) ? tA : tB;
        const uint32_t* wbase = g_wh32 + (size_t)t * 16384;
        const uint32_t* aggT = sAgg + it * AGGW;
        const float* bias = (t == 0) ? b0 : (t == 1) ? b1 : (t == 2) ? b2 : (t == 3) ? b3 : b4;

        __syncthreads();                  // prior epilogue's sSS reads complete
        if (tid < 128) sSS[tid] = 0.f;

        float c[4][4][4];
#pragma unroll
        for (int a = 0; a < 4; a++)
#pragma unroll
            for (int bb2 = 0; bb2 < 4; bb2++)
#pragma unroll
                for (int r = 0; r < 4; r++) c[a][bb2][r] = 0.f;

        uint4 st0, st1;
        auto load_stage = [&](int kt) {
            if (!isW) {
                if (kt < 8) {
                    int m = m0 + lr;
                    if (m < ndst) {
                        const uint32_t* src = g_xh32 + ((size_t)(xRowOff + m)) * 64 + kt * 8;
                        st0 = *(const uint4*)src;
                        st1 = *(const uint4*)(src + 4);
                    } else {
                        st0 = make_uint4(0, 0, 0, 0);
                        st1 = st0;
                    }
                }
            } else {
                const uint32_t* src = wbase + ((kt >= 8) ? 8192 : 0) + lr * 64 + (kt & 7) * 8;
                st0 = *(const uint4*)src;
                st1 = *(const uint4*)(src + 4);
            }
        };
        auto store_stage = [&](int buf, int kt) {
            if (!isW) {
                if (kt < 8) {
                    uint32_t* s = sX + buf * 1536 + lr * SROW;
                    *(uint4*)s = st0;
                    *(uint4*)(s + 4) = st1;
                }
            } else {
                uint32_t* s = sW + buf * 1536 + lr * SROW;
                *(uint4*)s = st0;
                *(uint4*)(s + 4) = st1;
            }
        };

        load_stage(0);
        store_stage(0, 0);
        __syncthreads();

        for (int kt = 0; kt < 16; kt++) {
            int cur = kt & 1;
            if (kt < 15) load_stage(kt + 1);

            const uint32_t* sWc = sW + cur * 1536;
            uint32_t Bf[4][2];
            if (kt < 8) {
                const uint32_t* sXc = sX + cur * 1536;
#pragma unroll
                for (int mt = 0; mt < 4; mt++) {
                    int base = (warpM * 32 + mt * 8 + g) * SROW + tg;
                    Bf[mt][0] = sXc[base];
                    Bf[mt][1] = sXc[base + 4];
                }
            } else {
#pragma unroll
                for (int mt = 0; mt < 4; mt++) {
                    int base = (warpM * 32 + mt * 8 + g) * AROW + (kt - 8) * 8 + tg;
                    Bf[mt][0] = aggT[base];
                    Bf[mt][1] = aggT[base + 4];
                }
            }
#pragma unroll
            for (int nt = 0; nt < 4; nt++) {
                int rw = (warpN * 64 + nt * 16 + g) * SROW + tg;
                uint32_t a0 = sWc[rw];
                uint32_t a1 = sWc[rw + 8 * SROW];
                uint32_t a2 = sWc[rw + 4];
                uint32_t a3 = sWc[rw + 8 * SROW + 4];
#pragma unroll
                for (int mt = 0; mt < 4; mt++) {
                    asm volatile(
                        "mma.sync.aligned.m16n8k16.row.col.f32.f16.f16.f32 "
                        "{%0,%1,%2,%3}, {%4,%5,%6,%7}, {%8,%9}, {%0,%1,%2,%3};\n"
                        : "+f"(c[nt][mt][0]), "+f"(c[nt][mt][1]),
                          "+f"(c[nt][mt][2]), "+f"(c[nt][mt][3])
                        : "r"(a0), "r"(a1), "r"(a2), "r"(a3),
                          "r"(Bf[mt][0]), "r"(Bf[mt][1]));
                }
            }

            if (kt < 15) {
                store_stage(cur ^ 1, kt + 1);
                __syncthreads();
            }
        }

        // ---- epilogue: bias, per-row L2 norm, store (it==0) or RMW add (it==1) ----
        float bias_v[4][2];
#pragma unroll
        for (int nt = 0; nt < 4; nt++) {
            int n = warpN * 64 + nt * 16 + g;
            bias_v[nt][0] = __ldg(&bias[n]);
            bias_v[nt][1] = __ldg(&bias[n + 8]);
        }
#pragma unroll
        for (int nt = 0; nt < 4; nt++)
#pragma unroll
            for (int mt = 0; mt < 4; mt++)
#pragma unroll
                for (int r = 0; r < 4; r++)
                    c[nt][mt][r] += bias_v[nt][r >> 1];

        float ps[4][2];
#pragma unroll
        for (int mt = 0; mt < 4; mt++)
#pragma unroll
            for (int j = 0; j < 2; j++) {
                float s = 0.f;
#pragma unroll
                for (int nt = 0; nt < 4; nt++) {
                    float v0 = c[nt][mt][j];
                    float v1 = c[nt][mt][2 + j];
                    s += v0 * v0 + v1 * v1;
                }
                s += __shfl_xor_sync(0xFFFFFFFFu, s, 4);
                s += __shfl_xor_sync(0xFFFFFFFFu, s, 8);
                s += __shfl_xor_sync(0xFFFFFFFFu, s, 16);
                ps[mt][j] = s;
            }
        if (g == 0) {
#pragma unroll
            for (int mt = 0; mt < 4; mt++)
#pragma unroll
                for (int j = 0; j < 2; j++)
                    atomicAdd(&sSS[warpM * 32 + mt * 8 + 2 * tg + j], ps[mt][j]);
        }
        __syncthreads();

#pragma unroll
        for (int mt = 0; mt < 4; mt++) {
#pragma unroll
            for (int j = 0; j < 2; j++) {
                int mloc = warpM * 32 + mt * 8 + 2 * tg + j;
                int m = m0 + mloc;
                if (m >= ndst) continue;
                float nrm = sqrtf(sSS[mloc]);
                float scale = 1.0f / fmaxf(nrm, 1e-12f);
                float* orow = osec + (size_t)m * DD;
#pragma unroll
                for (int nt = 0; nt < 4; nt++) {
#pragma unroll
                    for (int h = 0; h < 2; h++) {
                        int n = warpN * 64 + nt * 16 + g + h * 8;
                        float v = c[nt][mt][2 * h + j] * scale;
                        if (it > 0) v += orow[n];
                        orow[n] = v;
                    }
                }
            }
        }
    }
}

extern "C" void kernel_launch(void* const* d_in, const int* in_sizes, int n_in,
                              void* d_out, int out_size)
{
    const float* xa = (const float*)d_in[0];
    const float* xe = (const float*)d_in[1];
    const float* xf = (const float*)d_in[2];

    const int* si[5];
    const int* di[5];
    for (int t = 0; t < 5; t++) {
        si[t] = (const int*)d_in[3 + 2 * t];
        di[t] = (const int*)d_in[4 + 2 * t];
    }
    const float* wl[5];
    const float* bb[5];
    const float* wr[5];
    for (int t = 0; t < 5; t++) {
        wl[t] = (const float*)d_in[13 + 3 * t];
        bb[t] = (const float*)d_in[14 + 3 * t];
        wr[t] = (const float*)d_in[15 + 3 * t];
    }

    float* out = (float*)d_out;

    // ---- merged pre-pass: x->fp16 + zero cnt + w->fp16 ----
    {
        dim3 gp((NE * 32 + 255) / 256, 5);
        k_pre<<<gp, 256>>>(xa, xe, xf,
                           wl[0], wr[0], wl[1], wr[1], wl[2], wr[2], wl[3], wr[3], wl[4], wr[4]);
    }

    // ---- batched CSR build ----
    {
        dim3 gh((NEDGE + 255) / 256, 5);
        k_hist<<<gh, 256>>>(di[0], di[1], di[2], di[3], di[4]);
    }
    int nb = (TOTDST + 4095) / 4096;
    k_scan1<<<nb, 1024>>>();
    k_scan2<<<1, 256>>>(nb);
    k_scan3<<<(TOTDST + 255) / 256, 256>>>();
    {
        dim3 gh((NEDGE + 255) / 256, 5);
        k_scatter<<<gh, 256>>>(si[0], si[1], si[2], si[3], si[4],
                               di[0], di[1], di[2], di[3], di[4]);
    }

    // ---- fused aggregate + GEMM + normalize + combine (single launch) ----
    const int SMEM_BYTES = SMEM_WORDS * 4;   // 94,784 B
    cudaFuncSetAttribute(k_fused, cudaFuncAttributeMaxDynamicSharedMemorySize, SMEM_BYTES);
    k_fused<<<AB + EB + AB, 256, SMEM_BYTES>>>(bb[0], bb[1], bb[2], bb[3], bb[4], out);
}

// round 11
// speedup vs baseline: 1.0445x; 1.0445x over previous
#include <cuda_runtime.h>
#include <cuda_fp16.h>
#include <cstdint>

#define NA 100000
#define NE 200000
#define NF 100000
#define DD 128
#define NEDGE 400000
#define TOTDST 700000
#define TOTEDGE 2000000
#define TOTSRC 400000   // xa + xe + xf rows

// ---------------- scratch (device globals: allocation-free) ----------------
__device__ uint32_t g_xh32[(size_t)TOTSRC * 64];   // 102.4 MB  [xa|xe|xf] rows x 128 halves
__device__ uint32_t g_wh32[5 * 2 * 8192];          // 5 types x {wl,wr} x 128x128 halves
__device__ int   g_cnt[TOTDST];
__device__ int   g_rowstart[TOTDST];
__device__ int   g_cursor[TOTDST];
__device__ int   g_edge_src[TOTEDGE];
__device__ int   g_bsums[256];

// ---------------- merged pre-pass: x->fp16 (y=0..2), zero cnt (y=3), w->fp16 (y=4) ----------------
__global__ void k_pre(const float* __restrict__ xa, const float* __restrict__ xe,
                      const float* __restrict__ xf,
                      const float* p0, const float* p1, const float* p2, const float* p3,
                      const float* p4, const float* p5, const float* p6, const float* p7,
                      const float* p8, const float* p9) {
    int y = blockIdx.y;
    int i = blockIdx.x * 256 + threadIdx.x;
    if (y < 3) {
        const float* src = (y == 0) ? xa : (y == 1) ? xe : xf;
        int rows = (y == 1) ? NE : NA;
        size_t dstoff = (y == 0) ? 0 : (y == 1) ? (size_t)NA * 32 : (size_t)(NA + NE) * 32;
        if (i >= rows * 32) return;
        float4 v = ((const float4*)src)[i];
        __half2 a = __floats2half2_rn(v.x, v.y);
        __half2 b = __floats2half2_rn(v.z, v.w);
        uint32_t* d = g_xh32 + dstoff * 2 + (size_t)i * 2;
        d[0] = *(uint32_t*)&a;
        d[1] = *(uint32_t*)&b;
    } else if (y == 3) {
        if (i < TOTDST) g_cnt[i] = 0;
    } else {
        if (i >= 10 * 4096) return;
        int j = i >> 12;
        int w = i & 4095;
        const float* src = (j == 0) ? p0 : (j == 1) ? p1 : (j == 2) ? p2 : (j == 3) ? p3 :
                           (j == 4) ? p4 : (j == 5) ? p5 : (j == 6) ? p6 : (j == 7) ? p7 :
                           (j == 8) ? p8 : p9;
        float4 v = ((const float4*)src)[w];
        __half2 a = __floats2half2_rn(v.x, v.y);
        __half2 b = __floats2half2_rn(v.z, v.w);
        uint32_t* d = g_wh32 + (size_t)j * 8192 + (size_t)w * 2;
        d[0] = *(uint32_t*)&a;
        d[1] = *(uint32_t*)&b;
    }
}

// ---------------- batched CSR build ----------------
__device__ __forceinline__ int dst_off_of(int t) {
    return (t == 0) ? 0 : (t == 1) ? 200000 : (t == 2) ? 300000 : (t == 3) ? 400000 : 500000;
}

__global__ void k_hist(const int* d0, const int* d1, const int* d2, const int* d3, const int* d4) {
    int e = blockIdx.x * 256 + threadIdx.x;
    if (e >= NEDGE) return;
    int t = blockIdx.y;
    const int* di = (t == 0) ? d0 : (t == 1) ? d1 : (t == 2) ? d2 : (t == 3) ? d3 : d4;
    atomicAdd(&g_cnt[dst_off_of(t) + di[e]], 1);
}

__global__ void k_scan1() {
    __shared__ int s[1024];
    int t = threadIdx.x;
    int base = blockIdx.x * 4096;
    int v[4];
    int sum = 0;
#pragma unroll
    for (int j = 0; j < 4; j++) {
        int idx = base + t * 4 + j;
        v[j] = (idx < TOTDST) ? g_cnt[idx] : 0;
        sum += v[j];
    }
    s[t] = sum;
    __syncthreads();
    for (int off = 1; off < 1024; off <<= 1) {
        int x = (t >= off) ? s[t - off] : 0;
        __syncthreads();
        if (t >= off) s[t] += x;
        __syncthreads();
    }
    int excl = s[t] - sum;
    if (t == 1023) g_bsums[blockIdx.x] = s[1023];
    int run = excl;
#pragma unroll
    for (int j = 0; j < 4; j++) {
        int idx = base + t * 4 + j;
        if (idx < TOTDST) g_rowstart[idx] = run;
        run += v[j];
    }
}

__global__ void k_scan2(int nb) {
    __shared__ int s[256];
    int t = threadIdx.x;
    int v = (t < nb) ? g_bsums[t] : 0;
    s[t] = v;
    __syncthreads();
    for (int off = 1; off < 256; off <<= 1) {
        int x = (t >= off) ? s[t - off] : 0;
        __syncthreads();
        s[t] += x;
        __syncthreads();
    }
    if (t < nb) g_bsums[t] = s[t] - v;
}

__global__ void k_scan3() {
    int i = blockIdx.x * blockDim.x + threadIdx.x;
    if (i < TOTDST) {
        int r = g_rowstart[i] + g_bsums[i >> 12];
        g_rowstart[i] = r;
        g_cursor[i] = r;
    }
}

__global__ void k_scatter(const int* s0, const int* s1, const int* s2, const int* s3, const int* s4,
                          const int* d0, const int* d1, const int* d2, const int* d3, const int* d4) {
    int e = blockIdx.x * 256 + threadIdx.x;
    if (e >= NEDGE) return;
    int t = blockIdx.y;
    const int* si = (t == 0) ? s0 : (t == 1) ? s1 : (t == 2) ? s2 : (t == 3) ? s3 : s4;
    const int* di = (t == 0) ? d0 : (t == 1) ? d1 : (t == 2) ? d2 : (t == 3) ? d3 : d4;
    int d = dst_off_of(t) + di[e];
    int p = atomicAdd(&g_cursor[d], 1);
    g_edge_src[p] = si[e];
}

// ---------------- fused aggregate + dual-type GEMM + normalize + combine ----------------
// Phase A (R9 geometry): 4 rows/warp, 8 lanes x 32B per row, edge unroll-4
// (8 outstanding LDG.128/lane), PLUS next-row descriptor prefetch to pipeline
// the rowstart/cnt loads off the critical path.
// Phase B: two K=256 GEMMs back-to-back.

#define SROW 12      // staged-tile row stride (words)
#define AROW 68      // agg tile row stride (words); 68 mod 32 == 4 -> conflict-free frags
#define AGGW 8704    // words per agg tile (128 x AROW)
#define AB 782       // ceil(NA/128)
#define EB 1563      // ceil(NE/128)
#define SMEM_WORDS (6144 + 2 * AGGW + 128)

__global__ __launch_bounds__(256, 2)
void k_fused(const float* __restrict__ b0, const float* __restrict__ b1,
             const float* __restrict__ b2, const float* __restrict__ b3,
             const float* __restrict__ b4, float* __restrict__ out)
{
    extern __shared__ uint32_t dyn[];
    uint32_t* sW   = dyn;                    // 2 x 1536
    uint32_t* sX   = dyn + 3072;             // 2 x 1536
    uint32_t* sAgg = dyn + 6144;             // 2 x 8704
    float*    sSS  = (float*)(dyn + 6144 + 2 * AGGW);  // 128

    const int tid = threadIdx.x;
    const int lane = tid & 31;
    const int warpId = tid >> 5;
    const int warpN = warpId & 1;
    const int warpM = warpId >> 1;
    const int g = lane >> 2;
    const int tg = lane & 3;

    int b = blockIdx.x;
    int kind, mblk;
    if (b < AB) { kind = 0; mblk = b; }
    else if (b < AB + EB) { kind = 1; mblk = b - AB; }
    else { kind = 2; mblk = b - (AB + EB); }
    const int m0 = mblk * 128;
    const int ndst = (kind == 1) ? NE : NA;
    const size_t xRowOff = (kind == 0) ? 0 : (kind == 1) ? (size_t)NA : (size_t)(NA + NE);
    float* osec = out + ((kind == 0) ? 0 : (kind == 1) ? (size_t)NA * DD : (size_t)(NA + NE) * DD);
    const int tA = (kind == 0) ? 2 : (kind == 1) ? 0 : 1;
    const int tB = (kind == 0) ? -1 : (kind == 1) ? 4 : 3;
    const int ntypes = (kind == 0) ? 1 : 2;

    const int lr = tid & 127;
    const bool isW = tid >= 128;

    // ---- phase A: aggregate (both types); 4 rows/warp, 8 lanes x 32B per row;
    //      next-row (start,cnt) prefetched one iteration ahead ----
    {
        int rowsel = lane >> 3;   // 0..3: which of the warp's 4 concurrent rows
        int l8 = lane & 7;        // 0..7: 32B slice within the 256B row
        int total = 128 * ntypes;

        auto row_desc = [&](int rrq, int& start_o, int& cnt_o) {
            int itq = rrq >> 7;
            int rq = rrq & 127;
            int tq = (itq == 0) ? tA : tB;
            int mq = m0 + rq;
            if (mq < ndst) {
                int gid = dst_off_of(tq) + mq;
                start_o = __ldg(&g_rowstart[gid]);
                cnt_o = __ldg(&g_cnt[gid]);
            } else {
                start_o = 0;
                cnt_o = 0;
            }
        };

        int rr = warpId * 4 + rowsel;
        int pf_start = 0, pf_cnt = 0;
        if (rr < total) row_desc(rr, pf_start, pf_cnt);

        for (; rr < total; rr += 32) {
            int start = pf_start, cnt = pf_cnt;
            if (rr + 32 < total) row_desc(rr + 32, pf_start, pf_cnt);   // prefetch next

            int it = rr >> 7;
            int r = rr & 127;
            int t = (it == 0) ? tA : tB;
            size_t sOff = (t <= 1) ? 0 : (t <= 3) ? (size_t)NA : (size_t)(NA + NE);
            float f[16];
#pragma unroll
            for (int q = 0; q < 16; q++) f[q] = 0.f;

            for (int jb = 0; jb < cnt; jb += 4) {
                int ss[4];
                uint4 v0[4], v1[4];
#pragma unroll
                for (int k = 0; k < 4; k++)
                    ss[k] = (jb + k < cnt) ? __ldg(&g_edge_src[start + jb + k]) : -1;
#pragma unroll
                for (int k = 0; k < 4; k++) {
                    if (ss[k] >= 0) {
                        const uint4* p = (const uint4*)(g_xh32 + ((size_t)sOff + ss[k]) * 64 + l8 * 8);
                        v0[k] = __ldg(p);
                        v1[k] = __ldg(p + 1);
                    } else {
                        v0[k] = make_uint4(0, 0, 0, 0);
                        v1[k] = v0[k];
                    }
                }
#pragma unroll
                for (int k = 0; k < 4; k++) {
                    __half2 h; float2 q;
                    h = *(__half2*)&v0[k].x; q = __half22float2(h); f[0]  += q.x; f[1]  += q.y;
                    h = *(__half2*)&v0[k].y; q = __half22float2(h); f[2]  += q.x; f[3]  += q.y;
                    h = *(__half2*)&v0[k].z; q = __half22float2(h); f[4]  += q.x; f[5]  += q.y;
                    h = *(__half2*)&v0[k].w; q = __half22float2(h); f[6]  += q.x; f[7]  += q.y;
                    h = *(__half2*)&v1[k].x; q = __half22float2(h); f[8]  += q.x; f[9]  += q.y;
                    h = *(__half2*)&v1[k].y; q = __half22float2(h); f[10] += q.x; f[11] += q.y;
                    h = *(__half2*)&v1[k].z; q = __half22float2(h); f[12] += q.x; f[13] += q.y;
                    h = *(__half2*)&v1[k].w; q = __half22float2(h); f[14] += q.x; f[15] += q.y;
                }
            }

            float inv = 1.0f / (float)(cnt > 1 ? cnt : 1);
            uint4 o0, o1;
            {
                __half2 h0 = __floats2half2_rn(f[0] * inv,  f[1] * inv);  o0.x = *(uint32_t*)&h0;
                __half2 h1 = __floats2half2_rn(f[2] * inv,  f[3] * inv);  o0.y = *(uint32_t*)&h1;
                __half2 h2 = __floats2half2_rn(f[4] * inv,  f[5] * inv);  o0.z = *(uint32_t*)&h2;
                __half2 h3 = __floats2half2_rn(f[6] * inv,  f[7] * inv);  o0.w = *(uint32_t*)&h3;
                __half2 h4 = __floats2half2_rn(f[8] * inv,  f[9] * inv);  o1.x = *(uint32_t*)&h4;
                __half2 h5 = __floats2half2_rn(f[10] * inv, f[11] * inv); o1.y = *(uint32_t*)&h5;
                __half2 h6 = __floats2half2_rn(f[12] * inv, f[13] * inv); o1.z = *(uint32_t*)&h6;
                __half2 h7 = __floats2half2_rn(f[14] * inv, f[15] * inv); o1.w = *(uint32_t*)&h7;
            }
            uint4* dst = (uint4*)(sAgg + it * AGGW + r * AROW + l8 * 8);
            dst[0] = o0;
            dst[1] = o1;
        }
    }
    __syncthreads();

    // ---- phase B: per type, K=256 GEMM + epilogue ----
    for (int it = 0; it < ntypes; it++) {
        const int t = (it == 0) ? tA : tB;
        const uint32_t* wbase = g_wh32 + (size_t)t * 16384;
        const uint32_t* aggT = sAgg + it * AGGW;
        const float* bias = (t == 0) ? b0 : (t == 1) ? b1 : (t == 2) ? b2 : (t == 3) ? b3 : b4;

        __syncthreads();                  // prior epilogue's sSS reads complete
        if (tid < 128) sSS[tid] = 0.f;

        float c[4][4][4];
#pragma unroll
        for (int a = 0; a < 4; a++)
#pragma unroll
            for (int bb2 = 0; bb2 < 4; bb2++)
#pragma unroll
                for (int r = 0; r < 4; r++) c[a][bb2][r] = 0.f;

        uint4 st0, st1;
        auto load_stage = [&](int kt) {
            if (!isW) {
                if (kt < 8) {
                    int m = m0 + lr;
                    if (m < ndst) {
                        const uint32_t* src = g_xh32 + ((size_t)(xRowOff + m)) * 64 + kt * 8;
                        st0 = *(const uint4*)src;
                        st1 = *(const uint4*)(src + 4);
                    } else {
                        st0 = make_uint4(0, 0, 0, 0);
                        st1 = st0;
                    }
                }
            } else {
                const uint32_t* src = wbase + ((kt >= 8) ? 8192 : 0) + lr * 64 + (kt & 7) * 8;
                st0 = *(const uint4*)src;
                st1 = *(const uint4*)(src + 4);
            }
        };
        auto store_stage = [&](int buf, int kt) {
            if (!isW) {
                if (kt < 8) {
                    uint32_t* s = sX + buf * 1536 + lr * SROW;
                    *(uint4*)s = st0;
                    *(uint4*)(s + 4) = st1;
                }
            } else {
                uint32_t* s = sW + buf * 1536 + lr * SROW;
                *(uint4*)s = st0;
                *(uint4*)(s + 4) = st1;
            }
        };

        load_stage(0);
        store_stage(0, 0);
        __syncthreads();

        for (int kt = 0; kt < 16; kt++) {
            int cur = kt & 1;
            if (kt < 15) load_stage(kt + 1);

            const uint32_t* sWc = sW + cur * 1536;
            uint32_t Bf[4][2];
            if (kt < 8) {
                const uint32_t* sXc = sX + cur * 1536;
#pragma unroll
                for (int mt = 0; mt < 4; mt++) {
                    int base = (warpM * 32 + mt * 8 + g) * SROW + tg;
                    Bf[mt][0] = sXc[base];
                    Bf[mt][1] = sXc[base + 4];
                }
            } else {
#pragma unroll
                for (int mt = 0; mt < 4; mt++) {
                    int base = (warpM * 32 + mt * 8 + g) * AROW + (kt - 8) * 8 + tg;
                    Bf[mt][0] = aggT[base];
                    Bf[mt][1] = aggT[base + 4];
                }
            }
#pragma unroll
            for (int nt = 0; nt < 4; nt++) {
                int rw = (warpN * 64 + nt * 16 + g) * SROW + tg;
                uint32_t a0 = sWc[rw];
                uint32_t a1 = sWc[rw + 8 * SROW];
                uint32_t a2 = sWc[rw + 4];
                uint32_t a3 = sWc[rw + 8 * SROW + 4];
#pragma unroll
                for (int mt = 0; mt < 4; mt++) {
                    asm volatile(
                        "mma.sync.aligned.m16n8k16.row.col.f32.f16.f16.f32 "
                        "{%0,%1,%2,%3}, {%4,%5,%6,%7}, {%8,%9}, {%0,%1,%2,%3};\n"
                        : "+f"(c[nt][mt][0]), "+f"(c[nt][mt][1]),
                          "+f"(c[nt][mt][2]), "+f"(c[nt][mt][3])
                        : "r"(a0), "r"(a1), "r"(a2), "r"(a3),
                          "r"(Bf[mt][0]), "r"(Bf[mt][1]));
                }
            }

            if (kt < 15) {
                store_stage(cur ^ 1, kt + 1);
                __syncthreads();
            }
        }

        // ---- epilogue: bias, per-row L2 norm, store (it==0) or RMW add (it==1) ----
        float bias_v[4][2];
#pragma unroll
        for (int nt = 0; nt < 4; nt++) {
            int n = warpN * 64 + nt * 16 + g;
            bias_v[nt][0] = __ldg(&bias[n]);
            bias_v[nt][1] = __ldg(&bias[n + 8]);
        }
#pragma unroll
        for (int nt = 0; nt < 4; nt++)
#pragma unroll
            for (int mt = 0; mt < 4; mt++)
#pragma unroll
                for (int r = 0; r < 4; r++)
                    c[nt][mt][r] += bias_v[nt][r >> 1];

        float ps[4][2];
#pragma unroll
        for (int mt = 0; mt < 4; mt++)
#pragma unroll
            for (int j = 0; j < 2; j++) {
                float s = 0.f;
#pragma unroll
                for (int nt = 0; nt < 4; nt++) {
                    float v0 = c[nt][mt][j];
                    float v1 = c[nt][mt][2 + j];
                    s += v0 * v0 + v1 * v1;
                }
                s += __shfl_xor_sync(0xFFFFFFFFu, s, 4);
                s += __shfl_xor_sync(0xFFFFFFFFu, s, 8);
                s += __shfl_xor_sync(0xFFFFFFFFu, s, 16);
                ps[mt][j] = s;
            }
        if (g == 0) {
#pragma unroll
            for (int mt = 0; mt < 4; mt++)
#pragma unroll
                for (int j = 0; j < 2; j++)
                    atomicAdd(&sSS[warpM * 32 + mt * 8 + 2 * tg + j], ps[mt][j]);
        }
        __syncthreads();

#pragma unroll
        for (int mt = 0; mt < 4; mt++) {
#pragma unroll
            for (int j = 0; j < 2; j++) {
                int mloc = warpM * 32 + mt * 8 + 2 * tg + j;
                int m = m0 + mloc;
                if (m >= ndst) continue;
                float nrm = sqrtf(sSS[mloc]);
                float scale = 1.0f / fmaxf(nrm, 1e-12f);
                float* orow = osec + (size_t)m * DD;
#pragma unroll
                for (int nt = 0; nt < 4; nt++) {
#pragma unroll
                    for (int h = 0; h < 2; h++) {
                        int n = warpN * 64 + nt * 16 + g + h * 8;
                        float v = c[nt][mt][2 * h + j] * scale;
                        if (it > 0) v += orow[n];
                        orow[n] = v;
                    }
                }
            }
        }
    }
}

extern "C" void kernel_launch(void* const* d_in, const int* in_sizes, int n_in,
                              void* d_out, int out_size)
{
    const float* xa = (const float*)d_in[0];
    const float* xe = (const float*)d_in[1];
    const float* xf = (const float*)d_in[2];

    const int* si[5];
    const int* di[5];
    for (int t = 0; t < 5; t++) {
        si[t] = (const int*)d_in[3 + 2 * t];
        di[t] = (const int*)d_in[4 + 2 * t];
    }
    const float* wl[5];
    const float* bb[5];
    const float* wr[5];
    for (int t = 0; t < 5; t++) {
        wl[t] = (const float*)d_in[13 + 3 * t];
        bb[t] = (const float*)d_in[14 + 3 * t];
        wr[t] = (const float*)d_in[15 + 3 * t];
    }

    float* out = (float*)d_out;

    // ---- merged pre-pass: x->fp16 + zero cnt + w->fp16 ----
    {
        dim3 gp((NE * 32 + 255) / 256, 5);
        k_pre<<<gp, 256>>>(xa, xe, xf,
                           wl[0], wr[0], wl[1], wr[1], wl[2], wr[2], wl[3], wr[3], wl[4], wr[4]);
    }

    // ---- batched CSR build ----
    {
        dim3 gh((NEDGE + 255) / 256, 5);
        k_hist<<<gh, 256>>>(di[0], di[1], di[2], di[3], di[4]);
    }
    int nb = (TOTDST + 4095) / 4096;
    k_scan1<<<nb, 1024>>>();
    k_scan2<<<1, 256>>>(nb);
    k_scan3<<<(TOTDST + 255) / 256, 256>>>();
    {
        dim3 gh((NEDGE + 255) / 256, 5);
        k_scatter<<<gh, 256>>>(si[0], si[1], si[2], si[3], si[4],
                               di[0], di[1], di[2], di[3], di[4]);
    }

    // ---- fused aggregate + GEMM + normalize + combine (single launch) ----
    const int SMEM_BYTES = SMEM_WORDS * 4;   // 94,784 B
    cudaFuncSetAttribute(k_fused, cudaFuncAttributeMaxDynamicSharedMemorySize, SMEM_BYTES);
    k_fused<<<AB + EB + AB, 256, SMEM_BYTES>>>(bb[0], bb[1], bb[2], bb[3], bb[4], out);
}